// round 1
// baseline (speedup 1.0000x reference)
#include <cuda_runtime.h>
#include <cuda_bf16.h>
#include <cstdint>

// Problem constants: B=2, Q=KV=2048, D=1024, H=16, DH=64
#define BB     2
#define QQ     2048
#define KVN    2048
#define DD     1024
#define HH     16
#define DH     64
#define MROWS  (BB*QQ)          // 4096 rows for q (and k, since Q==KV)
#define EPS_F  1.1920928955078125e-07f

// ---------------- scratch (device globals; no cudaMalloc allowed) ----------
__device__ float g_qT0[DD * MROWS];            // normalized q, transposed [k][m]   16.8 MB
__device__ float g_kT0[DD * MROWS];            // normalized k, transposed [k][m]   16.8 MB
__device__ float g_WqT[DD * DD];               // Wq^T with wq_norm folded [k][n]    4 MB
__device__ float g_WkT[DD * DD];               // Wk^T with wk_norm folded [k][n]    4 MB
__device__ float g_qT[BB * DD * QQ];           // projected q, [b][h*64+d][i]       16.8 MB
__device__ float g_kT[BB * DD * KVN];          // projected k, [b][h*64+d][j]       16.8 MB
__device__ float g_scores[(size_t)BB*HH*QQ*KVN]; // per-head scores [bh][i][j]      536 MB
__device__ float g_m[BB*HH*QQ];                // row max
__device__ float g_l[BB*HH*QQ];                // row sumexp
__device__ float g_attnT[(size_t)BB*KVN*QQ];   // head-avg attn, TRANSPOSED [b][j][i] 33.5 MB

// ---------------- K0: weight transpose + rmsnorm-weight fold ---------------
// WT[k][n] = W[n][k] * wnorm[k]
__global__ void wtrans_kernel(const float* __restrict__ Wq, const float* __restrict__ Wk,
                              const float* __restrict__ wqn, const float* __restrict__ wkn) {
    const float* W  = blockIdx.z ? Wk  : Wq;
    const float* wn = blockIdx.z ? wkn : wqn;
    float*       O  = blockIdx.z ? g_WkT : g_WqT;
    int n0 = blockIdx.x * 32, k0 = blockIdx.y * 32;
    __shared__ float T[32][33];
    int r2 = threadIdx.x >> 5, c2 = threadIdx.x & 31;
#pragma unroll
    for (int e = 0; e < 4; ++e)
        T[r2 + 8*e][c2] = W[(size_t)(n0 + r2 + 8*e) * DD + k0 + c2];
    __syncthreads();
#pragma unroll
    for (int e = 0; e < 4; ++e) {
        int kk = k0 + r2 + 8*e;
        O[(size_t)kk * DD + n0 + c2] = T[c2][r2 + 8*e] * wn[kk];
    }
}

// ---------------- K1: rmsnorm scale + transpose ----------------------------
// out[k][m] = x[m][k] * rsqrt(mean_k(x^2)+eps)   (weight folded into WT)
__global__ void rmsnorm_t_kernel(const float* __restrict__ q, const float* __restrict__ k) {
    const float* x = blockIdx.y == 0 ? q : k;
    float*       o = blockIdx.y == 0 ? g_qT0 : g_kT0;
    int m0 = blockIdx.x * 32;
    int t = threadIdx.x;
    int r = t >> 3, l = t & 7;        // 32 rows x 8 lanes
    const float* row = x + (size_t)(m0 + r) * DD;
    float ss = 0.f;
#pragma unroll 8
    for (int u = 0; u < 32; ++u) {
        float4 v = *(const float4*)(row + l*4 + u*32);
        ss += v.x*v.x + v.y*v.y + v.z*v.z + v.w*v.w;
    }
    ss += __shfl_xor_sync(0xffffffffu, ss, 1);
    ss += __shfl_xor_sync(0xffffffffu, ss, 2);
    ss += __shfl_xor_sync(0xffffffffu, ss, 4);
    __shared__ float scale_s[32];
    if (l == 0) scale_s[r] = rsqrtf(ss * (1.0f/(float)DD) + EPS_F);
    __shared__ float T[32][33];
    int r2 = t >> 5, c2 = t & 31;
    for (int kc = 0; kc < 32; ++kc) {
        __syncthreads();
#pragma unroll
        for (int e = 0; e < 4; ++e)
            T[r2 + 8*e][c2] = x[(size_t)(m0 + r2 + 8*e) * DD + kc*32 + c2];
        __syncthreads();
#pragma unroll
        for (int e = 0; e < 4; ++e)
            o[(size_t)(kc*32 + r2 + 8*e) * MROWS + m0 + c2] = T[c2][r2 + 8*e] * scale_s[c2];
    }
}

// ---------------- K2/K6: TN GEMM -------------------------------------------
// C[m][n] = sum_k A[k][m] * B[k][n]  (+ bias[n] in MODE 1)
// MODE 0: C row-major [m][n], ldc = N  (attn @ value)
// MODE 1: store transposed into qT layout: C[(b*1024 + n)*2048 + (m&2047)], b=m>>11
template <int MODE>
__global__ void __launch_bounds__(256) gemm_tn_kernel(
    const float* __restrict__ A, const float* __restrict__ B,
    const float* __restrict__ bias, float* __restrict__ C,
    int N, int K, int lda, int ldb,
    long aStride, long bStride, long cStride) {
    A += (long)blockIdx.z * aStride;
    B += (long)blockIdx.z * bStride;
    C += (long)blockIdx.z * cStride;
    int n0 = blockIdx.x * 128, m0 = blockIdx.y * 128;
    __shared__ float As[16][128], Bs[16][128];
    int t = threadIdx.x;
    int tx = t & 15, ty = t >> 4;
    int lrow = t >> 5, lcg = t & 31;
    float acc[8][8];
#pragma unroll
    for (int i = 0; i < 8; ++i)
#pragma unroll
        for (int j = 0; j < 8; ++j) acc[i][j] = 0.f;

    for (int k0 = 0; k0 < K; k0 += 16) {
        float4 a0 = *(const float4*)(A + (size_t)(k0 + lrow    ) * lda + m0 + lcg*4);
        float4 a1 = *(const float4*)(A + (size_t)(k0 + lrow + 8) * lda + m0 + lcg*4);
        float4 b0 = *(const float4*)(B + (size_t)(k0 + lrow    ) * ldb + n0 + lcg*4);
        float4 b1 = *(const float4*)(B + (size_t)(k0 + lrow + 8) * ldb + n0 + lcg*4);
        __syncthreads();
        *(float4*)&As[lrow    ][lcg*4] = a0;
        *(float4*)&As[lrow + 8][lcg*4] = a1;
        *(float4*)&Bs[lrow    ][lcg*4] = b0;
        *(float4*)&Bs[lrow + 8][lcg*4] = b1;
        __syncthreads();
#pragma unroll
        for (int k = 0; k < 16; ++k) {
            float4 pa0 = *(const float4*)&As[k][ty*8];
            float4 pa1 = *(const float4*)&As[k][ty*8 + 4];
            float4 pb0 = *(const float4*)&Bs[k][tx*8];
            float4 pb1 = *(const float4*)&Bs[k][tx*8 + 4];
            float av[8] = {pa0.x, pa0.y, pa0.z, pa0.w, pa1.x, pa1.y, pa1.z, pa1.w};
            float bv[8] = {pb0.x, pb0.y, pb0.z, pb0.w, pb1.x, pb1.y, pb1.z, pb1.w};
#pragma unroll
            for (int i = 0; i < 8; ++i)
#pragma unroll
                for (int j = 0; j < 8; ++j)
                    acc[i][j] += av[i] * bv[j];
        }
    }

    if (MODE == 0) {
#pragma unroll
        for (int i = 0; i < 8; ++i) {
            float4 v0 = {acc[i][0], acc[i][1], acc[i][2], acc[i][3]};
            float4 v1 = {acc[i][4], acc[i][5], acc[i][6], acc[i][7]};
            float* p = C + (size_t)(m0 + ty*8 + i) * N + n0 + tx*8;
            *(float4*)(p)     = v0;
            *(float4*)(p + 4) = v1;
        }
    } else {
        int m  = m0 + ty*8;
        int b  = m >> 11;         // batch (rows per batch = 2048, BM=128 never crosses)
        int ii = m & 2047;
#pragma unroll
        for (int j = 0; j < 8; ++j) {
            int n = n0 + tx*8 + j;
            float bv = bias[n];
            float4 v0 = {acc[0][j] + bv, acc[1][j] + bv, acc[2][j] + bv, acc[3][j] + bv};
            float4 v1 = {acc[4][j] + bv, acc[5][j] + bv, acc[6][j] + bv, acc[7][j] + bv};
            float* p = C + ((size_t)(b * DD + n)) * QQ + ii;
            *(float4*)(p)     = v0;
            *(float4*)(p + 4) = v1;
        }
    }
}

// ---------------- K3: per-head scores --------------------------------------
// S[bh][i][j] = 0.125 * sum_d qT[b][h*64+d][i] * kT[b][h*64+d][j]
__global__ void __launch_bounds__(256) scores_kernel() {
    int bh = blockIdx.z;
    int b = bh >> 4, h = bh & 15;
    int i0 = blockIdx.y * 64, j0 = blockIdx.x * 128;
    __shared__ float Qs[64][64];
    __shared__ float Ks[64][128];
    int t = threadIdx.x;
    const float* qbase = g_qT + (size_t)(b * DD + h * DH) * QQ;
    const float* kbase = g_kT + (size_t)(b * DD + h * DH) * KVN;
#pragma unroll
    for (int l = 0; l < 4; ++l) {
        int idx = t + 256*l; int row = idx >> 4, cg = idx & 15;
        *(float4*)&Qs[row][cg*4] = *(const float4*)(qbase + (size_t)row * QQ + i0 + cg*4);
    }
#pragma unroll
    for (int l = 0; l < 8; ++l) {
        int idx = t + 256*l; int row = idx >> 5, cg = idx & 31;
        *(float4*)&Ks[row][cg*4] = *(const float4*)(kbase + (size_t)row * KVN + j0 + cg*4);
    }
    __syncthreads();
    int tx = t & 15, ty = t >> 4;     // ty*4 rows (i), tx*8 cols (j)
    float acc[4][8];
#pragma unroll
    for (int i = 0; i < 4; ++i)
#pragma unroll
        for (int j = 0; j < 8; ++j) acc[i][j] = 0.f;
#pragma unroll
    for (int k = 0; k < 64; ++k) {
        float4 pa  = *(const float4*)&Qs[k][ty*4];
        float4 pb0 = *(const float4*)&Ks[k][tx*8];
        float4 pb1 = *(const float4*)&Ks[k][tx*8 + 4];
        float av[4] = {pa.x, pa.y, pa.z, pa.w};
        float bv[8] = {pb0.x, pb0.y, pb0.z, pb0.w, pb1.x, pb1.y, pb1.z, pb1.w};
#pragma unroll
        for (int i = 0; i < 4; ++i)
#pragma unroll
            for (int j = 0; j < 8; ++j)
                acc[i][j] += av[i] * bv[j];
    }
    float* sbase = g_scores + ((size_t)bh * QQ + i0 + ty*4) * KVN + j0 + tx*8;
#pragma unroll
    for (int i = 0; i < 4; ++i) {
        float4 v0 = {acc[i][0]*0.125f, acc[i][1]*0.125f, acc[i][2]*0.125f, acc[i][3]*0.125f};
        float4 v1 = {acc[i][4]*0.125f, acc[i][5]*0.125f, acc[i][6]*0.125f, acc[i][7]*0.125f};
        float* p = sbase + (size_t)i * KVN;
        *(float4*)(p)     = v0;
        *(float4*)(p + 4) = v1;
    }
}

// ---------------- K4: per-row max & sumexp ---------------------------------
__global__ void rowstats_kernel() {
    size_t r = blockIdx.x;
    const float* row = g_scores + r * KVN;
    int t = threadIdx.x;
    float4 v0 = *(const float4*)(row + t*8);
    float4 v1 = *(const float4*)(row + t*8 + 4);
    float vv[8] = {v0.x, v0.y, v0.z, v0.w, v1.x, v1.y, v1.z, v1.w};
    float m = vv[0];
#pragma unroll
    for (int i = 1; i < 8; ++i) m = fmaxf(m, vv[i]);
    __shared__ float red[256];
    red[t] = m; __syncthreads();
    for (int s = 128; s > 0; s >>= 1) {
        if (t < s) red[t] = fmaxf(red[t], red[t + s]);
        __syncthreads();
    }
    m = red[0];
    __syncthreads();
    float sum = 0.f;
#pragma unroll
    for (int i = 0; i < 8; ++i) sum += __expf(vv[i] - m);
    red[t] = sum; __syncthreads();
    for (int s = 128; s > 0; s >>= 1) {
        if (t < s) red[t] += red[t + s];
        __syncthreads();
    }
    if (t == 0) { g_m[r] = m; g_l[r] = red[0]; }
}

// ---------------- K5: head-averaged attention (transposed write) -----------
// attnT[b][j][i] = (1/16) * sum_h exp(S[bh][i][j] - m[bh][i]) / l[bh][i]
__global__ void __launch_bounds__(256) attn_kernel() {
    int b = blockIdx.z;
    int i0 = blockIdx.y * 32;
    int j0 = blockIdx.x * 256;
    int t = threadIdx.x;
    __shared__ float m_s[16][32], il_s[16][32];
    for (int idx = t; idx < 512; idx += 256) {
        int h = idx >> 5, ii = idx & 31;
        size_t r = (size_t)(b*16 + h) * QQ + i0 + ii;
        m_s[h][ii]  = g_m[r];
        il_s[h][ii] = 1.0f / g_l[r];
    }
    __syncthreads();
    float acc[32];
#pragma unroll
    for (int ii = 0; ii < 32; ++ii) acc[ii] = 0.f;
    for (int h = 0; h < 16; ++h) {
        const float* p = g_scores + ((size_t)(b*16 + h) * QQ + i0) * KVN + j0 + t;
#pragma unroll
        for (int ii = 0; ii < 32; ++ii)
            acc[ii] += __expf(p[(size_t)ii * KVN] - m_s[h][ii]) * il_s[h][ii];
    }
    float* o = g_attnT + ((size_t)(b * KVN) + j0 + t) * QQ + i0;
#pragma unroll
    for (int ii = 0; ii < 32; ii += 4) {
        float4 v = {acc[ii]*0.0625f, acc[ii+1]*0.0625f, acc[ii+2]*0.0625f, acc[ii+3]*0.0625f};
        *(float4*)(o + ii) = v;
    }
}

// ---------------- launch ----------------------------------------------------
extern "C" void kernel_launch(void* const* d_in, const int* in_sizes, int n_in,
                              void* d_out, int out_size) {
    const float* query   = (const float*)d_in[0];
    const float* key     = (const float*)d_in[1];
    const float* value   = (const float*)d_in[2];
    const float* wq_norm = (const float*)d_in[3];
    const float* wk_norm = (const float*)d_in[4];
    const float* Wq      = (const float*)d_in[5];
    const float* Wk      = (const float*)d_in[6];
    const float* bq      = (const float*)d_in[7];
    const float* bk      = (const float*)d_in[8];
    float* out = (float*)d_out;

    float *qT0, *kT0, *WqT, *WkT, *qT, *kT, *attnT;
    cudaGetSymbolAddress((void**)&qT0,   g_qT0);
    cudaGetSymbolAddress((void**)&kT0,   g_kT0);
    cudaGetSymbolAddress((void**)&WqT,   g_WqT);
    cudaGetSymbolAddress((void**)&WkT,   g_WkT);
    cudaGetSymbolAddress((void**)&qT,    g_qT);
    cudaGetSymbolAddress((void**)&kT,    g_kT);
    cudaGetSymbolAddress((void**)&attnT, g_attnT);

    // K0: fold rmsnorm weight into transposed projection weights
    wtrans_kernel<<<dim3(32, 32, 2), 256>>>(Wq, Wk, wq_norm, wk_norm);
    // K1: rmsnorm + transpose inputs
    rmsnorm_t_kernel<<<dim3(MROWS/32, 2), 256>>>(query, key);
    // K2: projections (TN GEMM, bias, transposed store into per-head layout)
    gemm_tn_kernel<1><<<dim3(DD/128, MROWS/128), 256>>>(qT0, WqT, bq, qT,
        DD, DD, MROWS, DD, 0, 0, 0);
    gemm_tn_kernel<1><<<dim3(DD/128, MROWS/128), 256>>>(kT0, WkT, bk, kT,
        DD, DD, MROWS, DD, 0, 0, 0);
    // K3: per-head scores
    scores_kernel<<<dim3(KVN/128, QQ/64, BB*HH), 256>>>();
    // K4: softmax row stats
    rowstats_kernel<<<BB*HH*QQ, 256>>>();
    // K5: head-averaged attention, transposed
    attn_kernel<<<dim3(KVN/256, QQ/32, BB), 256>>>();
    // K6: features = attn @ value (TN GEMM per batch)
    gemm_tn_kernel<0><<<dim3(DD/128, QQ/128, BB), 256>>>(attnT, value, nullptr, out,
        DD, KVN, QQ, DD,
        (long)KVN * QQ, (long)KVN * DD, (long)QQ * DD);
}

// round 4
// speedup vs baseline: 1.3832x; 1.3832x over previous
#include <cuda_runtime.h>
#include <cuda_bf16.h>
#include <mma.h>
#include <cstdint>

using namespace nvcuda;

// Problem constants: B=2, Q=KV=2048, D=1024, H=16, DH=64
#define BB     2
#define QQ     2048
#define KVN    2048
#define DD     1024
#define HH     16
#define MROWS  (BB*QQ)
#define EPS_F  1.1920928955078125e-07f

// GEMM tiling
#define BM 128
#define BN 128
#define BK 32
#define APAD 36                  // padded row stride (floats)
#define NTILES (KVN / BN)        // 16 n-tiles for scores lpart

// smem layout (floats): As[2][128*36] | Bs[2][128*36]; epilogue reuses base as C[128*128]
#define S_A(buf)  ((buf) * (BM * APAD))
#define S_B(buf)  (2 * BM * APAD + (buf) * (BN * APAD))
#define SMEM_FLOATS (4 * BM * APAD)
#define SMEM_BYTES  (SMEM_FLOATS * 4)          // 73728

// ---------------- scratch ----------------------------------------------------
__device__ float g_qn[(size_t)MROWS * DD];
__device__ float g_kn[(size_t)MROWS * DD];
__device__ float g_Wqr[(size_t)DD * DD];
__device__ float g_Wkr[(size_t)DD * DD];
__device__ float g_qp[(size_t)MROWS * DD];
__device__ float g_kp[(size_t)MROWS * DD];
__device__ float g_vT[(size_t)BB * DD * KVN];
__device__ float g_scores[(size_t)BB * HH * QQ * KVN];   // holds exp(s/8)
__device__ float g_lpart[(size_t)BB * HH * QQ * NTILES]; // per-n-tile row sums
__device__ float g_attn[(size_t)BB * QQ * KVN];

// ---------------- helpers ----------------------------------------------------
__device__ __forceinline__ uint32_t smem_u32(const void* p) {
    uint32_t a;
    asm("{ .reg .u64 t; cvta.to.shared.u64 t, %1; cvt.u32.u64 %0, t; }" : "=r"(a) : "l"(p));
    return a;
}
// tf32 cvt writes a .b32 destination (NOT .f32) — keep the rounded bit pattern
__device__ __forceinline__ float to_tf32(float x) {
    uint32_t u;
    asm("cvt.rna.tf32.f32 %0, %1;" : "=r"(u) : "f"(x));
    return __uint_as_float(u);
}
#define CP_ASYNC16(dst_u32, src_ptr) \
    asm volatile("cp.async.ca.shared.global [%0], [%1], 16;" :: "r"(dst_u32), "l"(src_ptr))
#define CP_COMMIT() asm volatile("cp.async.commit_group;")
#define CP_WAIT1()  asm volatile("cp.async.wait_group 1;")
#define CP_WAIT0()  asm volatile("cp.async.wait_group 0;")

// ---------------- K: rmsnorm + fold norm-weight, round to tf32 ---------------
__global__ void rmsnorm_fold(const float* __restrict__ q, const float* __restrict__ k,
                             const float* __restrict__ wq, const float* __restrict__ wk) {
    const float* x; const float* w; float* o;
    if (blockIdx.y == 0) { x = q; w = wq; o = g_qn; } else { x = k; w = wk; o = g_kn; }
    size_t row = blockIdx.x;
    int t = threadIdx.x;
    const float* xr = x + row * DD;
    float4 v = *(const float4*)(xr + t * 4);
    float ss = v.x*v.x + v.y*v.y + v.z*v.z + v.w*v.w;
#pragma unroll
    for (int s = 16; s; s >>= 1) ss += __shfl_xor_sync(0xffffffffu, ss, s);
    __shared__ float red[8];
    if ((t & 31) == 0) red[t >> 5] = ss;
    __syncthreads();
    float tot = 0.f;
#pragma unroll
    for (int i = 0; i < 8; ++i) tot += red[i];
    float sc = rsqrtf(tot * (1.0f / (float)DD) + EPS_F);
    float4 wv = *(const float4*)(w + t * 4);
    float4 r;
    r.x = to_tf32(v.x * sc * wv.x); r.y = to_tf32(v.y * sc * wv.y);
    r.z = to_tf32(v.z * sc * wv.z); r.w = to_tf32(v.w * sc * wv.w);
    *(float4*)(o + row * DD + t * 4) = r;
}

// ---------------- K: round projection weights to tf32 ------------------------
__global__ void wprep(const float* __restrict__ Wq, const float* __restrict__ Wk) {
    const float* s = blockIdx.y ? Wk : Wq;
    float* o = blockIdx.y ? g_Wkr : g_Wqr;
    size_t i = (size_t)blockIdx.x * 1024 + threadIdx.x * 4;
    float4 v = *(const float4*)(s + i);
    v.x = to_tf32(v.x); v.y = to_tf32(v.y); v.z = to_tf32(v.z); v.w = to_tf32(v.w);
    *(float4*)(o + i) = v;
}

// ---------------- K: transpose value -> vT[b][d][j], round to tf32 -----------
__global__ void transpose_v(const float* __restrict__ v) {
    int b = blockIdx.z;
    int j0 = blockIdx.x * 32, d0 = blockIdx.y * 32;
    __shared__ float T[32][33];
    int tx = threadIdx.x, ty = threadIdx.y;
    const float* src = v + ((size_t)b * KVN + j0) * DD + d0;
#pragma unroll
    for (int e = 0; e < 4; ++e)
        T[ty + 8*e][tx] = src[(size_t)(ty + 8*e) * DD + tx];
    __syncthreads();
    float* dst = g_vT + ((size_t)b * DD + d0) * KVN + j0;
#pragma unroll
    for (int e = 0; e < 4; ++e)
        dst[(size_t)(ty + 8*e) * KVN + tx] = to_tf32(T[tx][ty + 8*e]);
}

// ---------------- wmma tf32 GEMM ---------------------------------------------
// D[M,N] = f(alpha * A[M,K] @ B[N,K]^T)   (A row-major, B row-major = Bt col-major)
// MODE 0: C = alpha*acc + bias (optional); rndC rounds stores to tf32
// MODE 1 (scores): C = exp(alpha*acc); per-row sums into lpart[...][blockIdx.x]
template <int MODE>
__global__ void __launch_bounds__(256, 2) gemm_mma(
    const float* __restrict__ A, const float* __restrict__ B,
    const float* __restrict__ bias, float* __restrict__ C, float* __restrict__ lpart,
    int K, int lda, int ldb, int ldc,
    long aStride, long bStride, long cStride, float alpha, int rndC) {
    extern __shared__ float smem[];
    uint32_t sb = smem_u32(smem);
    int t = threadIdx.x, warp = t >> 5;
    int wm = warp >> 2, wn = warp & 3;    // 2 x 4 warp grid; warp tile 64 x 32

    long z = blockIdx.z;
    const float *Ab, *Bb; float* Cb;
    if (MODE == 1) {
        long b = z >> 4, h = z & 15;
        Ab = A + b * aStride + h * 64;
        Bb = B + b * bStride + h * 64;
        Cb = C + z * cStride;
    } else {
        Ab = A + z * aStride; Bb = B + z * bStride; Cb = C + z * cStride;
    }
    int m0 = blockIdx.y * BM, n0 = blockIdx.x * BN;

    wmma::fragment<wmma::accumulator, 16, 16, 8, float> acc[4][2];
#pragma unroll
    for (int i = 0; i < 4; ++i)
#pragma unroll
        for (int j = 0; j < 2; ++j) wmma::fill_fragment(acc[i][j], 0.0f);

    int r0 = t >> 3;       // 0..31 (rows, stepped by 32)
    int c4 = t & 7;        // float4 column within 32-float K-slab

    // async loaders: tile c into buffer buf
    auto issue = [&](int c, int buf) {
        const float* Ag = Ab + (size_t)(m0 + r0) * lda + c * BK + c4 * 4;
        const float* Bg = Bb + (size_t)(n0 + r0) * ldb + c * BK + c4 * 4;
        uint32_t ad = sb + (S_A(buf) + r0 * APAD + c4 * 4) * 4;
        uint32_t bd = sb + (S_B(buf) + r0 * APAD + c4 * 4) * 4;
#pragma unroll
        for (int l = 0; l < 4; ++l)
            CP_ASYNC16(ad + l * 32 * APAD * 4, Ag + (size_t)(32 * l) * lda);
#pragma unroll
        for (int l = 0; l < 4; ++l)
            CP_ASYNC16(bd + l * 32 * APAD * 4, Bg + (size_t)(32 * l) * ldb);
    };

    int nc = K / BK;
    issue(0, 0); CP_COMMIT();
    for (int c = 0; c < nc; ++c) {
        if (c + 1 < nc) { issue(c + 1, (c + 1) & 1); CP_COMMIT(); CP_WAIT1(); }
        else           { CP_WAIT0(); }
        __syncthreads();
        const float* As = smem + S_A(c & 1);
        const float* Bs = smem + S_B(c & 1);
#pragma unroll
        for (int ks = 0; ks < BK / 8; ++ks) {
            wmma::fragment<wmma::matrix_a, 16, 16, 8, wmma::precision::tf32, wmma::row_major> af[4];
            wmma::fragment<wmma::matrix_b, 16, 16, 8, wmma::precision::tf32, wmma::col_major> bf[2];
#pragma unroll
            for (int i = 0; i < 4; ++i)
                wmma::load_matrix_sync(af[i], As + (wm * 64 + i * 16) * APAD + ks * 8, APAD);
#pragma unroll
            for (int j = 0; j < 2; ++j)
                wmma::load_matrix_sync(bf[j], Bs + (wn * 32 + j * 16) * APAD + ks * 8, APAD);
#pragma unroll
            for (int i = 0; i < 4; ++i)
#pragma unroll
                for (int j = 0; j < 2; ++j)
                    wmma::mma_sync(acc[i][j], af[i], bf[j], acc[i][j]);
        }
        __syncthreads();
    }

    // ---- epilogue: stage accumulators through smem, then elementwise ----
    float* Ct = smem;   // 128x128
#pragma unroll
    for (int i = 0; i < 4; ++i)
#pragma unroll
        for (int j = 0; j < 2; ++j)
            wmma::store_matrix_sync(Ct + (wm * 64 + i * 16) * BN + wn * 32 + j * 16,
                                    acc[i][j], BN, wmma::mem_row_major);
    __syncthreads();

    int r = t >> 1;                 // row 0..127
    int ch = (t & 1) * 64;          // column half
    const float* srow = Ct + r * BN + ch;
    float* crow = Cb + (size_t)(m0 + r) * ldc + n0 + ch;
    if (MODE == 1) {
        float rowsum = 0.f;
#pragma unroll
        for (int j = 0; j < 64; j += 4) {
            float4 v = *(const float4*)(srow + j);
            v.x = __expf(alpha * v.x); v.y = __expf(alpha * v.y);
            v.z = __expf(alpha * v.z); v.w = __expf(alpha * v.w);
            rowsum += (v.x + v.y) + (v.z + v.w);
            *(float4*)(crow + j) = v;
        }
        rowsum += __shfl_xor_sync(0xffffffffu, rowsum, 1);
        if ((t & 1) == 0)
            lpart[((size_t)z * QQ + m0 + r) * NTILES + blockIdx.x] = rowsum;
    } else {
#pragma unroll
        for (int j = 0; j < 64; j += 4) {
            float4 v = *(const float4*)(srow + j);
            float b0 = 0.f, b1 = 0.f, b2 = 0.f, b3 = 0.f;
            if (bias) {
                const float* bp = bias + n0 + ch + j;
                b0 = bp[0]; b1 = bp[1]; b2 = bp[2]; b3 = bp[3];
            }
            v.x = alpha * v.x + b0; v.y = alpha * v.y + b1;
            v.z = alpha * v.z + b2; v.w = alpha * v.w + b3;
            if (rndC) { v.x = to_tf32(v.x); v.y = to_tf32(v.y);
                        v.z = to_tf32(v.z); v.w = to_tf32(v.w); }
            *(float4*)(crow + j) = v;
        }
    }
}

// ---------------- K: head-average of exp'd scores ----------------------------
// attn[b][i][j] = (1/16) * sum_h escore[bh][i][j] / l[bh][i]
__global__ void __launch_bounds__(256) attn_avg() {
    int blk = blockIdx.x;
    int b = blk >> 11, i = blk & 2047;
    int t = threadIdx.x;
    __shared__ float il_s[16];
    if (t < 16) {
        const float* lp = g_lpart + ((size_t)(b * 16 + t) * QQ + i) * NTILES;
        float s = 0.f;
#pragma unroll
        for (int j = 0; j < NTILES; ++j) s += lp[j];
        il_s[t] = 1.0f / s;
    }
    __syncthreads();
    float acc[8];
#pragma unroll
    for (int j = 0; j < 8; ++j) acc[j] = 0.f;
    for (int h = 0; h < 16; ++h) {
        const float* p = g_scores + ((size_t)(b * 16 + h) * QQ + i) * KVN + t * 8;
        float il = il_s[h];
        float4 v0 = *(const float4*)(p);
        float4 v1 = *(const float4*)(p + 4);
        acc[0] += v0.x * il; acc[1] += v0.y * il; acc[2] += v0.z * il; acc[3] += v0.w * il;
        acc[4] += v1.x * il; acc[5] += v1.y * il; acc[6] += v1.z * il; acc[7] += v1.w * il;
    }
    float* o = g_attn + ((size_t)b * QQ + i) * KVN + t * 8;
    float4 w0, w1;
    w0.x = to_tf32(acc[0] * 0.0625f); w0.y = to_tf32(acc[1] * 0.0625f);
    w0.z = to_tf32(acc[2] * 0.0625f); w0.w = to_tf32(acc[3] * 0.0625f);
    w1.x = to_tf32(acc[4] * 0.0625f); w1.y = to_tf32(acc[5] * 0.0625f);
    w1.z = to_tf32(acc[6] * 0.0625f); w1.w = to_tf32(acc[7] * 0.0625f);
    *(float4*)(o)     = w0;
    *(float4*)(o + 4) = w1;
}

// ---------------- launch -----------------------------------------------------
extern "C" void kernel_launch(void* const* d_in, const int* in_sizes, int n_in,
                              void* d_out, int out_size) {
    const float* query   = (const float*)d_in[0];
    const float* key     = (const float*)d_in[1];
    const float* value   = (const float*)d_in[2];
    const float* wq_norm = (const float*)d_in[3];
    const float* wk_norm = (const float*)d_in[4];
    const float* Wq      = (const float*)d_in[5];
    const float* Wk      = (const float*)d_in[6];
    const float* bq      = (const float*)d_in[7];
    const float* bk      = (const float*)d_in[8];
    float* out = (float*)d_out;

    float *qn, *kn, *Wqr, *Wkr, *qp, *kp, *vT, *scores, *lpart, *attn;
    cudaGetSymbolAddress((void**)&qn, g_qn);
    cudaGetSymbolAddress((void**)&kn, g_kn);
    cudaGetSymbolAddress((void**)&Wqr, g_Wqr);
    cudaGetSymbolAddress((void**)&Wkr, g_Wkr);
    cudaGetSymbolAddress((void**)&qp, g_qp);
    cudaGetSymbolAddress((void**)&kp, g_kp);
    cudaGetSymbolAddress((void**)&vT, g_vT);
    cudaGetSymbolAddress((void**)&scores, g_scores);
    cudaGetSymbolAddress((void**)&lpart, g_lpart);
    cudaGetSymbolAddress((void**)&attn, g_attn);

    cudaFuncSetAttribute(gemm_mma<0>, cudaFuncAttributeMaxDynamicSharedMemorySize, SMEM_BYTES);
    cudaFuncSetAttribute(gemm_mma<1>, cudaFuncAttributeMaxDynamicSharedMemorySize, SMEM_BYTES);

    // prep
    rmsnorm_fold<<<dim3(MROWS, 2), 256>>>(query, key, wq_norm, wk_norm);
    wprep<<<dim3(DD * DD / 1024, 2), 256>>>(Wq, Wk);
    transpose_v<<<dim3(KVN / 32, DD / 32, BB), dim3(32, 8)>>>(value);

    // projections: qp = qn @ Wq^T + bq  (M=4096, N=1024, K=1024)
    gemm_mma<0><<<dim3(DD / BN, MROWS / BM, 1), 256, SMEM_BYTES>>>(
        qn, Wqr, bq, qp, nullptr, DD, DD, DD, DD, 0, 0, 0, 1.0f, 1);
    gemm_mma<0><<<dim3(DD / BN, MROWS / BM, 1), 256, SMEM_BYTES>>>(
        kn, Wkr, bk, kp, nullptr, DD, DD, DD, DD, 0, 0, 0, 1.0f, 1);

    // scores: escore[bh] = exp(0.125 * qp_h @ kp_h^T)  (M=2048, N=2048, K=64) x32
    gemm_mma<1><<<dim3(KVN / BN, QQ / BM, BB * HH), 256, SMEM_BYTES>>>(
        qp, kp, nullptr, scores, lpart, 64, DD, DD, KVN,
        (long)QQ * DD, (long)KVN * DD, (long)QQ * KVN, 0.125f, 0);

    // softmax normalize + head average
    attn_avg<<<BB * QQ, 256>>>();

    // out = attn @ value  (M=2048, N=1024, K=2048) x2
    gemm_mma<0><<<dim3(DD / BN, QQ / BM, BB), 256, SMEM_BYTES>>>(
        attn, vT, nullptr, out, nullptr, KVN, KVN, KVN, DD,
        (long)QQ * KVN, (long)DD * KVN, (long)QQ * DD, 1.0f, 0);
}

// round 5
// speedup vs baseline: 2.4129x; 1.7444x over previous
#include <cuda_runtime.h>
#include <cuda_fp16.h>
#include <mma.h>
#include <cstdint>

using namespace nvcuda;

// Problem constants: B=2, Q=KV=2048, D=1024, H=16, DH=64
#define BB     2
#define QQ     2048
#define KVN    2048
#define DD     1024
#define HH     16
#define MROWS  (BB*QQ)
#define EPS_F  1.1920928955078125e-07f

// GEMM tiling (fp16 operands, fp32 accum)
#define BM 128
#define BN 128
#define BK 64                    // 64 halves = 128B per row slab
#define APAD 72                  // padded row stride in halves (144B, LDSM-conflict-free)
#define NTILES (KVN / BN)        // 16 n-tiles for scores lpart

// smem layout in halves: As[2][128*72] | Bs[2][128*72]
// epilogue reuses base as float C[128*128] (64KB <= 72KB)
#define S_A(buf)  ((buf) * (BM * APAD))
#define S_B(buf)  (2 * BM * APAD + (buf) * (BN * APAD))
#define SMEM_HALVES (4 * BM * APAD)
#define SMEM_BYTES  (SMEM_HALVES * 2)          // 73728

// ---------------- scratch ----------------------------------------------------
__device__ __half g_qn[(size_t)MROWS * DD];
__device__ __half g_kn[(size_t)MROWS * DD];
__device__ __half g_Wqr[(size_t)DD * DD];
__device__ __half g_Wkr[(size_t)DD * DD];
__device__ __half g_qp[(size_t)MROWS * DD];
__device__ __half g_kp[(size_t)MROWS * DD];
__device__ __half g_vT[(size_t)BB * DD * KVN];
__device__ float  g_scores[(size_t)BB * HH * QQ * KVN];   // exp(s/8), fp32
__device__ float  g_lpart[(size_t)BB * HH * QQ * NTILES]; // per-n-tile row sums
__device__ __half g_attn[(size_t)BB * QQ * KVN];

// ---------------- helpers ----------------------------------------------------
__device__ __forceinline__ uint32_t smem_u32(const void* p) {
    uint32_t a;
    asm("{ .reg .u64 t; cvta.to.shared.u64 t, %1; cvt.u32.u64 %0, t; }" : "=r"(a) : "l"(p));
    return a;
}
#define CP_ASYNC16(dst_u32, src_ptr) \
    asm volatile("cp.async.ca.shared.global [%0], [%1], 16;" :: "r"(dst_u32), "l"(src_ptr))
#define CP_COMMIT() asm volatile("cp.async.commit_group;")
#define CP_WAIT1()  asm volatile("cp.async.wait_group 1;")
#define CP_WAIT0()  asm volatile("cp.async.wait_group 0;")

__device__ __forceinline__ uint32_t pack2(float a, float b) {
    __half2 h = __floats2half2_rn(a, b);
    return *reinterpret_cast<uint32_t*>(&h);
}

// ---------------- K: rmsnorm + fold norm-weight -> fp16 ----------------------
__global__ void rmsnorm_fold(const float* __restrict__ q, const float* __restrict__ k,
                             const float* __restrict__ wq, const float* __restrict__ wk) {
    const float* x; const float* w; __half* o;
    if (blockIdx.y == 0) { x = q; w = wq; o = g_qn; } else { x = k; w = wk; o = g_kn; }
    size_t row = blockIdx.x;
    int t = threadIdx.x;
    const float* xr = x + row * DD;
    float4 v = *(const float4*)(xr + t * 4);
    float ss = v.x*v.x + v.y*v.y + v.z*v.z + v.w*v.w;
#pragma unroll
    for (int s = 16; s; s >>= 1) ss += __shfl_xor_sync(0xffffffffu, ss, s);
    __shared__ float red[8];
    if ((t & 31) == 0) red[t >> 5] = ss;
    __syncthreads();
    float tot = 0.f;
#pragma unroll
    for (int i = 0; i < 8; ++i) tot += red[i];
    float sc = rsqrtf(tot * (1.0f / (float)DD) + EPS_F);
    float4 wv = *(const float4*)(w + t * 4);
    uint2 pkd;
    pkd.x = pack2(v.x * sc * wv.x, v.y * sc * wv.y);
    pkd.y = pack2(v.z * sc * wv.z, v.w * sc * wv.w);
    *(uint2*)(o + row * DD + t * 4) = pkd;
}

// ---------------- K: convert projection weights to fp16 ----------------------
__global__ void wprep(const float* __restrict__ Wq, const float* __restrict__ Wk) {
    const float* s = blockIdx.y ? Wk : Wq;
    __half* o = blockIdx.y ? g_Wkr : g_Wqr;
    size_t i = (size_t)blockIdx.x * 1024 + threadIdx.x * 4;
    float4 v = *(const float4*)(s + i);
    uint2 pkd;
    pkd.x = pack2(v.x, v.y);
    pkd.y = pack2(v.z, v.w);
    *(uint2*)(o + i) = pkd;
}

// ---------------- K: transpose value -> vT[b][d][j] fp16 ---------------------
__global__ void transpose_v(const float* __restrict__ v) {
    int b = blockIdx.z;
    int j0 = blockIdx.x * 32, d0 = blockIdx.y * 32;
    __shared__ float T[32][33];
    int tx = threadIdx.x, ty = threadIdx.y;
    const float* src = v + ((size_t)b * KVN + j0) * DD + d0;
#pragma unroll
    for (int e = 0; e < 4; ++e)
        T[ty + 8*e][tx] = src[(size_t)(ty + 8*e) * DD + tx];
    __syncthreads();
    __half* dst = g_vT + ((size_t)b * DD + d0) * KVN + j0;
#pragma unroll
    for (int e = 0; e < 4; ++e)
        dst[(size_t)(ty + 8*e) * KVN + tx] = __float2half_rn(T[tx][ty + 8*e]);
}

// ---------------- fp16 wmma GEMM ---------------------------------------------
// D[M,N] = f(alpha * A[M,K] @ B[N,K]^T), A/B fp16 row-major, acc fp32
// MODE 0: C = alpha*acc + bias (optional), OutT = __half or float
// MODE 1 (scores): C = exp(alpha*acc) (float), row sums into lpart[...][blockIdx.x]
template <int MODE, typename OutT>
__global__ void __launch_bounds__(256, 2) gemm_mma(
    const __half* __restrict__ A, const __half* __restrict__ B,
    const float* __restrict__ bias, OutT* __restrict__ C, float* __restrict__ lpart,
    int K, int lda, int ldb, int ldc,
    long aStride, long bStride, long cStride, float alpha) {
    extern __shared__ __half smem[];
    uint32_t sb = smem_u32(smem);
    int t = threadIdx.x, warp = t >> 5;
    int wm = warp >> 2, wn = warp & 3;    // 2 x 4 warp grid; warp tile 64 x 32

    long z = blockIdx.z;
    const __half *Ab, *Bb; OutT* Cb;
    if (MODE == 1) {
        long b = z >> 4, h = z & 15;
        Ab = A + b * aStride + h * 64;
        Bb = B + b * bStride + h * 64;
        Cb = C + z * cStride;
    } else {
        Ab = A + z * aStride; Bb = B + z * bStride; Cb = C + z * cStride;
    }
    int m0 = blockIdx.y * BM, n0 = blockIdx.x * BN;

    wmma::fragment<wmma::accumulator, 16, 16, 16, float> acc[4][2];
#pragma unroll
    for (int i = 0; i < 4; ++i)
#pragma unroll
        for (int j = 0; j < 2; ++j) wmma::fill_fragment(acc[i][j], 0.0f);

    int r0 = t >> 1;             // row 0..127
    int cb = (t & 1) * 32;       // half-column base (each thread: 4 x 8-half chunks)

    auto issue = [&](int c, int buf) {
        const __half* Ag = Ab + (size_t)(m0 + r0) * lda + c * BK + cb;
        const __half* Bg = Bb + (size_t)(n0 + r0) * ldb + c * BK + cb;
        uint32_t ad = sb + (S_A(buf) + r0 * APAD + cb) * 2;
        uint32_t bd = sb + (S_B(buf) + r0 * APAD + cb) * 2;
#pragma unroll
        for (int l = 0; l < 4; ++l) CP_ASYNC16(ad + l * 16, Ag + l * 8);
#pragma unroll
        for (int l = 0; l < 4; ++l) CP_ASYNC16(bd + l * 16, Bg + l * 8);
    };

    int nc = K / BK;
    issue(0, 0); CP_COMMIT();
    for (int c = 0; c < nc; ++c) {
        if (c + 1 < nc) { issue(c + 1, (c + 1) & 1); CP_COMMIT(); CP_WAIT1(); }
        else           { CP_WAIT0(); }
        __syncthreads();
        const __half* As = smem + S_A(c & 1);
        const __half* Bs = smem + S_B(c & 1);
#pragma unroll
        for (int ks = 0; ks < BK / 16; ++ks) {
            wmma::fragment<wmma::matrix_a, 16, 16, 16, __half, wmma::row_major> af[4];
            wmma::fragment<wmma::matrix_b, 16, 16, 16, __half, wmma::col_major> bf[2];
#pragma unroll
            for (int i = 0; i < 4; ++i)
                wmma::load_matrix_sync(af[i], As + (wm * 64 + i * 16) * APAD + ks * 16, APAD);
#pragma unroll
            for (int j = 0; j < 2; ++j)
                wmma::load_matrix_sync(bf[j], Bs + (wn * 32 + j * 16) * APAD + ks * 16, APAD);
#pragma unroll
            for (int i = 0; i < 4; ++i)
#pragma unroll
                for (int j = 0; j < 2; ++j)
                    wmma::mma_sync(acc[i][j], af[i], bf[j], acc[i][j]);
        }
        __syncthreads();
    }

    // ---- epilogue: stage accumulators through smem (fp32), then elementwise ----
    float* Ct = reinterpret_cast<float*>(smem);   // 128x128
#pragma unroll
    for (int i = 0; i < 4; ++i)
#pragma unroll
        for (int j = 0; j < 2; ++j)
            wmma::store_matrix_sync(Ct + (wm * 64 + i * 16) * BN + wn * 32 + j * 16,
                                    acc[i][j], BN, wmma::mem_row_major);
    __syncthreads();

    int r = t >> 1;                 // row 0..127
    int ch = (t & 1) * 64;          // column half
    const float* srow = Ct + r * BN + ch;
    if (MODE == 1) {
        float* crow = (float*)Cb + (size_t)(m0 + r) * ldc + n0 + ch;
        float rowsum = 0.f;
#pragma unroll
        for (int j = 0; j < 64; j += 4) {
            float4 v = *(const float4*)(srow + j);
            v.x = __expf(alpha * v.x); v.y = __expf(alpha * v.y);
            v.z = __expf(alpha * v.z); v.w = __expf(alpha * v.w);
            rowsum += (v.x + v.y) + (v.z + v.w);
            *(float4*)(crow + j) = v;
        }
        rowsum += __shfl_xor_sync(0xffffffffu, rowsum, 1);
        if ((t & 1) == 0)
            lpart[((size_t)z * QQ + m0 + r) * NTILES + blockIdx.x] = rowsum;
    } else {
        OutT* crow = Cb + (size_t)(m0 + r) * ldc + n0 + ch;
#pragma unroll
        for (int j = 0; j < 64; j += 4) {
            float4 v = *(const float4*)(srow + j);
            float b0 = 0.f, b1 = 0.f, b2 = 0.f, b3 = 0.f;
            if (bias) {
                const float* bp = bias + n0 + ch + j;
                b0 = bp[0]; b1 = bp[1]; b2 = bp[2]; b3 = bp[3];
            }
            v.x = alpha * v.x + b0; v.y = alpha * v.y + b1;
            v.z = alpha * v.z + b2; v.w = alpha * v.w + b3;
            if (sizeof(OutT) == 2) {
                uint2 pkd; pkd.x = pack2(v.x, v.y); pkd.y = pack2(v.z, v.w);
                *(uint2*)(crow + j) = pkd;
            } else {
                *(float4*)((float*)crow + j) = v;
            }
        }
    }
}

// ---------------- K: head-average of exp'd scores -> fp16 attn ---------------
// attn[b][i][j] = (1/16) * sum_h escore[bh][i][j] / l[bh][i]
__global__ void __launch_bounds__(256) attn_avg() {
    int blk = blockIdx.x;
    int b = blk >> 11, i = blk & 2047;
    int t = threadIdx.x;
    __shared__ float il_s[16];
    if (t < 16) {
        const float* lp = g_lpart + ((size_t)(b * 16 + t) * QQ + i) * NTILES;
        float s = 0.f;
#pragma unroll
        for (int j = 0; j < NTILES; ++j) s += lp[j];
        il_s[t] = 1.0f / s;
    }
    __syncthreads();
    float acc[8];
#pragma unroll
    for (int j = 0; j < 8; ++j) acc[j] = 0.f;
    for (int h = 0; h < 16; ++h) {
        const float* p = g_scores + ((size_t)(b * 16 + h) * QQ + i) * KVN + t * 8;
        float il = il_s[h];
        float4 v0 = *(const float4*)(p);
        float4 v1 = *(const float4*)(p + 4);
        acc[0] += v0.x * il; acc[1] += v0.y * il; acc[2] += v0.z * il; acc[3] += v0.w * il;
        acc[4] += v1.x * il; acc[5] += v1.y * il; acc[6] += v1.z * il; acc[7] += v1.w * il;
    }
    __half* o = g_attn + ((size_t)b * QQ + i) * KVN + t * 8;
    uint4 pkd;
    pkd.x = pack2(acc[0] * 0.0625f, acc[1] * 0.0625f);
    pkd.y = pack2(acc[2] * 0.0625f, acc[3] * 0.0625f);
    pkd.z = pack2(acc[4] * 0.0625f, acc[5] * 0.0625f);
    pkd.w = pack2(acc[6] * 0.0625f, acc[7] * 0.0625f);
    *(uint4*)o = pkd;
}

// ---------------- launch -----------------------------------------------------
extern "C" void kernel_launch(void* const* d_in, const int* in_sizes, int n_in,
                              void* d_out, int out_size) {
    const float* query   = (const float*)d_in[0];
    const float* key     = (const float*)d_in[1];
    const float* value   = (const float*)d_in[2];
    const float* wq_norm = (const float*)d_in[3];
    const float* wk_norm = (const float*)d_in[4];
    const float* Wq      = (const float*)d_in[5];
    const float* Wk      = (const float*)d_in[6];
    const float* bq      = (const float*)d_in[7];
    const float* bk      = (const float*)d_in[8];
    float* out = (float*)d_out;

    __half *qn, *kn, *Wqr, *Wkr, *qp, *kp, *vT, *attn;
    float *scores, *lpart;
    cudaGetSymbolAddress((void**)&qn, g_qn);
    cudaGetSymbolAddress((void**)&kn, g_kn);
    cudaGetSymbolAddress((void**)&Wqr, g_Wqr);
    cudaGetSymbolAddress((void**)&Wkr, g_Wkr);
    cudaGetSymbolAddress((void**)&qp, g_qp);
    cudaGetSymbolAddress((void**)&kp, g_kp);
    cudaGetSymbolAddress((void**)&vT, g_vT);
    cudaGetSymbolAddress((void**)&scores, g_scores);
    cudaGetSymbolAddress((void**)&lpart, g_lpart);
    cudaGetSymbolAddress((void**)&attn, g_attn);

    cudaFuncSetAttribute((const void*)gemm_mma<0, __half>,
                         cudaFuncAttributeMaxDynamicSharedMemorySize, SMEM_BYTES);
    cudaFuncSetAttribute((const void*)gemm_mma<0, float>,
                         cudaFuncAttributeMaxDynamicSharedMemorySize, SMEM_BYTES);
    cudaFuncSetAttribute((const void*)gemm_mma<1, float>,
                         cudaFuncAttributeMaxDynamicSharedMemorySize, SMEM_BYTES);

    // prep
    rmsnorm_fold<<<dim3(MROWS, 2), 256>>>(query, key, wq_norm, wk_norm);
    wprep<<<dim3(DD * DD / 1024, 2), 256>>>(Wq, Wk);
    transpose_v<<<dim3(KVN / 32, DD / 32, BB), dim3(32, 8)>>>(value);

    // projections: qp = qn @ Wq^T + bq  (M=4096, N=1024, K=1024) -> fp16
    gemm_mma<0, __half><<<dim3(DD / BN, MROWS / BM, 1), 256, SMEM_BYTES>>>(
        qn, Wqr, bq, qp, nullptr, DD, DD, DD, DD, 0, 0, 0, 1.0f);
    gemm_mma<0, __half><<<dim3(DD / BN, MROWS / BM, 1), 256, SMEM_BYTES>>>(
        kn, Wkr, bk, kp, nullptr, DD, DD, DD, DD, 0, 0, 0, 1.0f);

    // scores: escore[bh] = exp(0.125 * qp_h @ kp_h^T)  (M=2048, N=2048, K=64) x32
    gemm_mma<1, float><<<dim3(KVN / BN, QQ / BM, BB * HH), 256, SMEM_BYTES>>>(
        qp, kp, nullptr, scores, lpart, 64, DD, DD, KVN,
        (long)QQ * DD, (long)KVN * DD, (long)QQ * KVN, 0.125f);

    // softmax normalize + head average -> fp16 attn
    attn_avg<<<BB * QQ, 256>>>();

    // out = attn @ value  (M=2048, N=1024, K=2048) x2 -> fp32
    gemm_mma<0, float><<<dim3(DD / BN, QQ / BM, BB), 256, SMEM_BYTES>>>(
        attn, vT, nullptr, out, nullptr, KVN, KVN, KVN, DD,
        (long)QQ * KVN, (long)DD * KVN, (long)QQ * DD, 1.0f);
}

// round 7
// speedup vs baseline: 2.8981x; 1.2011x over previous
#include <cuda_runtime.h>
#include <cuda_fp16.h>
#include <mma.h>
#include <cstdint>

using namespace nvcuda;

// Problem constants: B=2, Q=KV=2048, D=1024, H=16, DH=64
#define BB     2
#define QQ     2048
#define KVN    2048
#define DD     1024
#define HH     16
#define MROWS  (BB*QQ)
#define EPS_F  1.1920928955078125e-07f

// GEMM tiling (fp16 operands, fp32 accum)
#define BM 128
#define BN 128
#define BK 64                    // 64 halves = 128B per row slab
#define APAD 72                  // padded row stride in halves
#define NTILES (KVN / BN)        // 16 n-tiles for scores lpart

// smem layout in halves: As[2][128*72] | Bs[2][128*72]
// epilogue reuses base as float C[128*128] (64KB <= 72KB)
#define S_A(buf)  ((buf) * (BM * APAD))
#define S_B(buf)  (2 * BM * APAD + (buf) * (BN * APAD))
#define SMEM_HALVES (4 * BM * APAD)
#define SMEM_BYTES  (SMEM_HALVES * 2)          // 73728

// ---------------- scratch ----------------------------------------------------
__device__ __half g_qn[(size_t)MROWS * DD];
__device__ __half g_kn[(size_t)MROWS * DD];
__device__ __half g_Wqr[(size_t)DD * DD];
__device__ __half g_Wkr[(size_t)DD * DD];
__device__ __half g_qp[(size_t)MROWS * DD];
__device__ __half g_kp[(size_t)MROWS * DD];
__device__ __half g_vT[(size_t)BB * DD * KVN];
__device__ __half g_scores[(size_t)BB * HH * QQ * KVN];   // exp(s/8), fp16 (268MB)
__device__ float  g_lpart[(size_t)BB * HH * QQ * NTILES]; // per-n-tile row sums
__device__ __half g_attn[(size_t)BB * QQ * KVN];

// ---------------- helpers ----------------------------------------------------
__device__ __forceinline__ uint32_t smem_u32(const void* p) {
    uint32_t a;
    asm("{ .reg .u64 t; cvta.to.shared.u64 t, %1; cvt.u32.u64 %0, t; }" : "=r"(a) : "l"(p));
    return a;
}
#define CP_ASYNC16(dst_u32, src_ptr) \
    asm volatile("cp.async.ca.shared.global [%0], [%1], 16;" :: "r"(dst_u32), "l"(src_ptr))
#define CP_COMMIT() asm volatile("cp.async.commit_group;")
#define CP_WAIT1()  asm volatile("cp.async.wait_group 1;")
#define CP_WAIT0()  asm volatile("cp.async.wait_group 0;")

__device__ __forceinline__ uint32_t pack2(float a, float b) {
    __half2 h = __floats2half2_rn(a, b);
    return *reinterpret_cast<uint32_t*>(&h);
}

// ---------------- K: rmsnorm + fold norm-weight -> fp16 ----------------------
__global__ void rmsnorm_fold(const float* __restrict__ q, const float* __restrict__ k,
                             const float* __restrict__ wq, const float* __restrict__ wk) {
    const float* x; const float* w; __half* o;
    if (blockIdx.y == 0) { x = q; w = wq; o = g_qn; } else { x = k; w = wk; o = g_kn; }
    size_t row = blockIdx.x;
    int t = threadIdx.x;
    const float* xr = x + row * DD;
    float4 v = *(const float4*)(xr + t * 4);
    float ss = v.x*v.x + v.y*v.y + v.z*v.z + v.w*v.w;
#pragma unroll
    for (int s = 16; s; s >>= 1) ss += __shfl_xor_sync(0xffffffffu, ss, s);
    __shared__ float red[8];
    if ((t & 31) == 0) red[t >> 5] = ss;
    __syncthreads();
    float tot = 0.f;
#pragma unroll
    for (int i = 0; i < 8; ++i) tot += red[i];
    float sc = rsqrtf(tot * (1.0f / (float)DD) + EPS_F);
    float4 wv = *(const float4*)(w + t * 4);
    uint2 pkd;
    pkd.x = pack2(v.x * sc * wv.x, v.y * sc * wv.y);
    pkd.y = pack2(v.z * sc * wv.z, v.w * sc * wv.w);
    *(uint2*)(o + row * DD + t * 4) = pkd;
}

// ---------------- K: convert projection weights to fp16 ----------------------
__global__ void wprep(const float* __restrict__ Wq, const float* __restrict__ Wk) {
    const float* s = blockIdx.y ? Wk : Wq;
    __half* o = blockIdx.y ? g_Wkr : g_Wqr;
    size_t i = (size_t)blockIdx.x * 1024 + threadIdx.x * 4;
    float4 v = *(const float4*)(s + i);
    uint2 pkd;
    pkd.x = pack2(v.x, v.y);
    pkd.y = pack2(v.z, v.w);
    *(uint2*)(o + i) = pkd;
}

// ---------------- K: transpose value -> vT[b][d][j] fp16 ---------------------
__global__ void transpose_v(const float* __restrict__ v) {
    int b = blockIdx.z;
    int j0 = blockIdx.x * 32, d0 = blockIdx.y * 32;
    __shared__ float T[32][33];
    int tx = threadIdx.x, ty = threadIdx.y;
    const float* src = v + ((size_t)b * KVN + j0) * DD + d0;
#pragma unroll
    for (int e = 0; e < 4; ++e)
        T[ty + 8*e][tx] = src[(size_t)(ty + 8*e) * DD + tx];
    __syncthreads();
    __half* dst = g_vT + ((size_t)b * DD + d0) * KVN + j0;
#pragma unroll
    for (int e = 0; e < 4; ++e)
        dst[(size_t)(ty + 8*e) * KVN + tx] = __float2half_rn(T[tx][ty + 8*e]);
}

// ---------------- fp16 wmma GEMM ---------------------------------------------
// D[M,N] = f(alpha * A[M,K] @ B[N,K]^T), A/B fp16 row-major, acc fp32
// MODE 0: C = alpha*acc + bias (optional), OutT = __half or float
// MODE 1 (scores): C = exp(alpha*acc) packed fp16; fp32 row sums -> lpart
template <int MODE, typename OutT>
__global__ void __launch_bounds__(256, 2) gemm_mma(
    const __half* __restrict__ A, const __half* __restrict__ B,
    const float* __restrict__ bias, OutT* __restrict__ C, float* __restrict__ lpart,
    int K, int lda, int ldb, int ldc,
    long aStride, long bStride, long cStride, float alpha) {
    extern __shared__ __half smem[];
    uint32_t sb = smem_u32(smem);
    int t = threadIdx.x, warp = t >> 5;
    int wm = warp >> 2, wn = warp & 3;    // 2 x 4 warp grid; warp tile 64 x 32

    long z = blockIdx.z;
    const __half *Ab, *Bb; OutT* Cb;
    if (MODE == 1) {
        long b = z >> 4, h = z & 15;
        Ab = A + b * aStride + h * 64;
        Bb = B + b * bStride + h * 64;
        Cb = C + z * cStride;
    } else {
        Ab = A + z * aStride; Bb = B + z * bStride; Cb = C + z * cStride;
    }
    int m0 = blockIdx.y * BM, n0 = blockIdx.x * BN;

    wmma::fragment<wmma::accumulator, 16, 16, 16, float> acc[4][2];
#pragma unroll
    for (int i = 0; i < 4; ++i)
#pragma unroll
        for (int j = 0; j < 2; ++j) wmma::fill_fragment(acc[i][j], 0.0f);

    int r0 = t >> 1;             // row 0..127
    int cb = (t & 1) * 32;       // half-column base (each thread: 4 x 8-half chunks)

    auto issue = [&](int c, int buf) {
        const __half* Ag = Ab + (size_t)(m0 + r0) * lda + c * BK + cb;
        const __half* Bg = Bb + (size_t)(n0 + r0) * ldb + c * BK + cb;
        uint32_t ad = sb + (S_A(buf) + r0 * APAD + cb) * 2;
        uint32_t bd = sb + (S_B(buf) + r0 * APAD + cb) * 2;
#pragma unroll
        for (int l = 0; l < 4; ++l) CP_ASYNC16(ad + l * 16, Ag + l * 8);
#pragma unroll
        for (int l = 0; l < 4; ++l) CP_ASYNC16(bd + l * 16, Bg + l * 8);
    };

    int nc = K / BK;
    issue(0, 0); CP_COMMIT();
    for (int c = 0; c < nc; ++c) {
        if (c + 1 < nc) { issue(c + 1, (c + 1) & 1); CP_COMMIT(); CP_WAIT1(); }
        else           { CP_WAIT0(); }
        __syncthreads();
        const __half* As = smem + S_A(c & 1);
        const __half* Bs = smem + S_B(c & 1);
#pragma unroll
        for (int ks = 0; ks < BK / 16; ++ks) {
            wmma::fragment<wmma::matrix_a, 16, 16, 16, __half, wmma::row_major> af[4];
            wmma::fragment<wmma::matrix_b, 16, 16, 16, __half, wmma::col_major> bf[2];
#pragma unroll
            for (int i = 0; i < 4; ++i)
                wmma::load_matrix_sync(af[i], As + (wm * 64 + i * 16) * APAD + ks * 16, APAD);
#pragma unroll
            for (int j = 0; j < 2; ++j)
                wmma::load_matrix_sync(bf[j], Bs + (wn * 32 + j * 16) * APAD + ks * 16, APAD);
#pragma unroll
            for (int i = 0; i < 4; ++i)
#pragma unroll
                for (int j = 0; j < 2; ++j)
                    wmma::mma_sync(acc[i][j], af[i], bf[j], acc[i][j]);
        }
        __syncthreads();
    }

    // ---- epilogue: stage accumulators through smem (fp32), then elementwise ----
    float* Ct = reinterpret_cast<float*>(smem);   // 128x128
#pragma unroll
    for (int i = 0; i < 4; ++i)
#pragma unroll
        for (int j = 0; j < 2; ++j)
            wmma::store_matrix_sync(Ct + (wm * 64 + i * 16) * BN + wn * 32 + j * 16,
                                    acc[i][j], BN, wmma::mem_row_major);
    __syncthreads();

    int r = t >> 1;                 // row 0..127
    int ch = (t & 1) * 64;          // column half
    const float* srow = Ct + r * BN + ch;
    if (MODE == 1) {
        __half* crow = (__half*)Cb + (size_t)(m0 + r) * ldc + n0 + ch;
        float rowsum = 0.f;
#pragma unroll
        for (int j = 0; j < 64; j += 8) {
            float4 v0 = *(const float4*)(srow + j);
            float4 v1 = *(const float4*)(srow + j + 4);
            float e0 = __expf(alpha * v0.x), e1 = __expf(alpha * v0.y);
            float e2 = __expf(alpha * v0.z), e3 = __expf(alpha * v0.w);
            float e4 = __expf(alpha * v1.x), e5 = __expf(alpha * v1.y);
            float e6 = __expf(alpha * v1.z), e7 = __expf(alpha * v1.w);
            rowsum += ((e0 + e1) + (e2 + e3)) + ((e4 + e5) + (e6 + e7));
            uint4 pkd;
            pkd.x = pack2(e0, e1); pkd.y = pack2(e2, e3);
            pkd.z = pack2(e4, e5); pkd.w = pack2(e6, e7);
            *(uint4*)(crow + j) = pkd;
        }
        rowsum += __shfl_xor_sync(0xffffffffu, rowsum, 1);
        if ((t & 1) == 0)
            lpart[((size_t)z * QQ + m0 + r) * NTILES + blockIdx.x] = rowsum;
    } else {
        OutT* crow = Cb + (size_t)(m0 + r) * ldc + n0 + ch;
#pragma unroll
        for (int j = 0; j < 64; j += 4) {
            float4 v = *(const float4*)(srow + j);
            float b0 = 0.f, b1 = 0.f, b2 = 0.f, b3 = 0.f;
            if (bias) {
                const float* bp = bias + n0 + ch + j;
                b0 = bp[0]; b1 = bp[1]; b2 = bp[2]; b3 = bp[3];
            }
            v.x = alpha * v.x + b0; v.y = alpha * v.y + b1;
            v.z = alpha * v.z + b2; v.w = alpha * v.w + b3;
            if (sizeof(OutT) == 2) {
                uint2 pkd; pkd.x = pack2(v.x, v.y); pkd.y = pack2(v.z, v.w);
                *(uint2*)(crow + j) = pkd;
            } else {
                *(float4*)((float*)crow + j) = v;
            }
        }
    }
}

// ---------------- K: head-average of exp'd fp16 scores -> fp16 attn ----------
// attn[b][i][j] = (1/16) * sum_h escore[bh][i][j] / l[bh][i]
__global__ void __launch_bounds__(256) attn_avg() {
    int blk = blockIdx.x;
    int b = blk >> 11, i = blk & 2047;
    int t = threadIdx.x;
    __shared__ float il_s[16];
    if (t < 16) {
        const float* lp = g_lpart + ((size_t)(b * 16 + t) * QQ + i) * NTILES;
        float s = 0.f;
#pragma unroll
        for (int j = 0; j < NTILES; ++j) s += lp[j];
        il_s[t] = 1.0f / s;
    }
    __syncthreads();
    float acc[8];
#pragma unroll
    for (int j = 0; j < 8; ++j) acc[j] = 0.f;
    for (int h = 0; h < 16; ++h) {
        const __half* p = g_scores + ((size_t)(b * 16 + h) * QQ + i) * KVN + t * 8;
        float il = il_s[h];
        uint4 raw = *(const uint4*)p;
        float2 f0 = __half22float2(*reinterpret_cast<__half2*>(&raw.x));
        float2 f1 = __half22float2(*reinterpret_cast<__half2*>(&raw.y));
        float2 f2 = __half22float2(*reinterpret_cast<__half2*>(&raw.z));
        float2 f3 = __half22float2(*reinterpret_cast<__half2*>(&raw.w));
        acc[0] += f0.x * il; acc[1] += f0.y * il;
        acc[2] += f1.x * il; acc[3] += f1.y * il;
        acc[4] += f2.x * il; acc[5] += f2.y * il;
        acc[6] += f3.x * il; acc[7] += f3.y * il;
    }
    __half* o = g_attn + ((size_t)b * QQ + i) * KVN + t * 8;
    uint4 pkd;
    pkd.x = pack2(acc[0] * 0.0625f, acc[1] * 0.0625f);
    pkd.y = pack2(acc[2] * 0.0625f, acc[3] * 0.0625f);
    pkd.z = pack2(acc[4] * 0.0625f, acc[5] * 0.0625f);
    pkd.w = pack2(acc[6] * 0.0625f, acc[7] * 0.0625f);
    *(uint4*)o = pkd;
}

// ---------------- launch -----------------------------------------------------
extern "C" void kernel_launch(void* const* d_in, const int* in_sizes, int n_in,
                              void* d_out, int out_size) {
    const float* query   = (const float*)d_in[0];
    const float* key     = (const float*)d_in[1];
    const float* value   = (const float*)d_in[2];
    const float* wq_norm = (const float*)d_in[3];
    const float* wk_norm = (const float*)d_in[4];
    const float* Wq      = (const float*)d_in[5];
    const float* Wk      = (const float*)d_in[6];
    const float* bq      = (const float*)d_in[7];
    const float* bk      = (const float*)d_in[8];
    float* out = (float*)d_out;

    __half *qn, *kn, *Wqr, *Wkr, *qp, *kp, *vT, *attn, *scores;
    float *lpart;
    cudaGetSymbolAddress((void**)&qn, g_qn);
    cudaGetSymbolAddress((void**)&kn, g_kn);
    cudaGetSymbolAddress((void**)&Wqr, g_Wqr);
    cudaGetSymbolAddress((void**)&Wkr, g_Wkr);
    cudaGetSymbolAddress((void**)&qp, g_qp);
    cudaGetSymbolAddress((void**)&kp, g_kp);
    cudaGetSymbolAddress((void**)&vT, g_vT);
    cudaGetSymbolAddress((void**)&scores, g_scores);
    cudaGetSymbolAddress((void**)&lpart, g_lpart);
    cudaGetSymbolAddress((void**)&attn, g_attn);

    cudaFuncSetAttribute((const void*)gemm_mma<0, __half>,
                         cudaFuncAttributeMaxDynamicSharedMemorySize, SMEM_BYTES);
    cudaFuncSetAttribute((const void*)gemm_mma<0, float>,
                         cudaFuncAttributeMaxDynamicSharedMemorySize, SMEM_BYTES);
    cudaFuncSetAttribute((const void*)gemm_mma<1, __half>,
                         cudaFuncAttributeMaxDynamicSharedMemorySize, SMEM_BYTES);

    // prep
    rmsnorm_fold<<<dim3(MROWS, 2), 256>>>(query, key, wq_norm, wk_norm);
    wprep<<<dim3(DD * DD / 1024, 2), 256>>>(Wq, Wk);
    transpose_v<<<dim3(KVN / 32, DD / 32, BB), dim3(32, 8)>>>(value);

    // projections: qp = qn @ Wq^T + bq  (M=4096, N=1024, K=1024) -> fp16
    gemm_mma<0, __half><<<dim3(DD / BN, MROWS / BM, 1), 256, SMEM_BYTES>>>(
        qn, Wqr, bq, qp, nullptr, DD, DD, DD, DD, 0, 0, 0, 1.0f);
    gemm_mma<0, __half><<<dim3(DD / BN, MROWS / BM, 1), 256, SMEM_BYTES>>>(
        kn, Wkr, bk, kp, nullptr, DD, DD, DD, DD, 0, 0, 0, 1.0f);

    // scores: escore[bh] = exp(0.125 * qp_h @ kp_h^T) fp16  (M=2048,N=2048,K=64) x32
    gemm_mma<1, __half><<<dim3(KVN / BN, QQ / BM, BB * HH), 256, SMEM_BYTES>>>(
        qp, kp, nullptr, scores, lpart, 64, DD, DD, KVN,
        (long)QQ * DD, (long)KVN * DD, (long)QQ * KVN, 0.125f);

    // softmax normalize + head average -> fp16 attn
    attn_avg<<<BB * QQ, 256>>>();

    // out = attn @ value  (M=2048, N=1024, K=2048) x2 -> fp32
    gemm_mma<0, float><<<dim3(DD / BN, QQ / BM, BB), 256, SMEM_BYTES>>>(
        attn, vT, nullptr, out, nullptr, KVN, KVN, KVN, DD,
        (long)QQ * KVN, (long)DD * KVN, (long)QQ * DD, 1.0f);
}